// round 12
// baseline (speedup 1.0000x reference)
#include <cuda_runtime.h>
#include <cuda_fp16.h>
#include <cstdint>

#define B_   2
#define S_   2048
#define D_   768
#define H_   12
#define HD_  64
#define NTOK (B_*S_)

// fp16 staging buffers
__device__ __half g_xh[NTOK*D_];     // X fp16 [m][k]
__device__ __half g_wt[3*D_*D_];     // W^T fp16 [z][n][k]
__device__ __half g_qh[NTOK*D_];     // [bh][s][64]
__device__ __half g_kh[NTOK*D_];
__device__ __half g_vh[NTOK*D_];

#define SWZ(b) ((b) ^ (((b)>>3)&0x70))

__device__ __forceinline__ uint32_t smem_u32(const void* p){
    uint32_t a;
    asm("{ .reg .u64 t; cvta.to.shared.u64 t, %1; cvt.u32.u64 %0, t; }" : "=r"(a) : "l"(p));
    return a;
}
__device__ __forceinline__ void ldsm4(uint32_t* r, uint32_t a){
    asm volatile("ldmatrix.sync.aligned.m8n8.x4.shared.b16 {%0,%1,%2,%3}, [%4];"
        : "=r"(r[0]),"=r"(r[1]),"=r"(r[2]),"=r"(r[3]) : "r"(a));
}
__device__ __forceinline__ void ldsm4t(uint32_t* r, uint32_t a){
    asm volatile("ldmatrix.sync.aligned.m8n8.x4.trans.shared.b16 {%0,%1,%2,%3}, [%4];"
        : "=r"(r[0]),"=r"(r[1]),"=r"(r[2]),"=r"(r[3]) : "r"(a));
}
__device__ __forceinline__ void mma16816(float* d, const uint32_t* a, const uint32_t* b){
    asm volatile(
        "mma.sync.aligned.m16n8k16.row.col.f32.f16.f16.f32 "
        "{%0,%1,%2,%3}, {%4,%5,%6,%7}, {%8,%9}, {%0,%1,%2,%3};"
        : "+f"(d[0]),"+f"(d[1]),"+f"(d[2]),"+f"(d[3])
        : "r"(a[0]),"r"(a[1]),"r"(a[2]),"r"(a[3]), "r"(b[0]),"r"(b[1]));
}
__device__ __forceinline__ uint32_t packh2(float x, float y){
    __half2 h = __floats2half2_rn(x, y);
    return *(uint32_t*)&h;
}
__device__ __forceinline__ float ex2(float x){
    float y; asm("ex2.approx.ftz.f32 %0, %1;" : "=f"(y) : "f"(x)); return y;
}
__device__ __forceinline__ void cpasync16(uint32_t dst, const void* src){
    asm volatile("cp.async.cg.shared.global [%0], [%1], 16;" :: "r"(dst), "l"(src));
}
#define CP_COMMIT() asm volatile("cp.async.commit_group;" ::: "memory")
#define CP_WAIT1()  asm volatile("cp.async.wait_group 1;" ::: "memory")
#define CP_WAIT0()  asm volatile("cp.async.wait_group 0;" ::: "memory")

#define LOG2E 1.4426950408889634f
#define SCL2E 0.1803368801111437f   /* 0.125 * log2(e) */

// ============================ convert X -> fp16 ============================
__global__ __launch_bounds__(256) void convert_x(const float* __restrict__ X){
    int i = (blockIdx.x * 256 + threadIdx.x) * 4;
    float4 v = *(const float4*)(X + i);
    uint2 u;
    u.x = packh2(v.x, v.y);
    u.y = packh2(v.z, v.w);
    *(uint2*)&g_xh[i] = u;
}

// ============================ convert W -> W^T fp16 ============================
__global__ __launch_bounds__(256) void convert_w(
    const float* __restrict__ Wq, const float* __restrict__ Wk, const float* __restrict__ Wv)
{
    __shared__ float t[32][33];
    const int z = blockIdx.z;
    const float* W = (z==0) ? Wq : (z==1) ? Wk : Wv;
    __half* out = g_wt + (size_t)z * D_ * D_;
    const int n0 = blockIdx.x * 32, k0 = blockIdx.y * 32;
    const int tx = threadIdx.x, ty = threadIdx.y;   // 32 x 8
#pragma unroll
    for (int i = 0; i < 32; i += 8)
        t[ty + i][tx] = W[(size_t)(k0 + ty + i) * D_ + n0 + tx];
    __syncthreads();
#pragma unroll
    for (int i = 0; i < 32; i += 8)
        out[(size_t)(n0 + ty + i) * D_ + k0 + tx] = __float2half_rn(t[tx][ty + i]);
}

// ============================ QKV GEMM (fp16 mma.sync, 3-stage cp.async) ============================
// block tile M=128 x N=128 (2 heads), K loop 768 in chunks of 64, 3-stage ring.
// 8 warps: 4(m) x 2(n), warp tile 32x64. 2 CTAs/SM (reg cap 128).
#define GEMM_SMEM 98304

__global__ __launch_bounds__(256, 2) void qkv_gemm_h(
    const float* __restrict__ bq, const float* __restrict__ bk, const float* __restrict__ bv)
{
    extern __shared__ char sm[];
    const uint32_t sA = smem_u32(sm);            // 3 x 16KB
    const uint32_t sB = sA + 49152;              // 3 x 16KB

    const int tid = threadIdx.x, wid = tid >> 5, lane = tid & 31;
    const int z  = blockIdx.z;
    const int m0 = blockIdx.x * 128;
    const int n0 = blockIdx.y * 128;

    const __half* Wth = g_wt + (size_t)z * D_ * D_;
    const float* bias = (z==0) ? bq : (z==1) ? bk : bv;
    __half* dst = (z==0) ? g_qh : (z==1) ? g_kh : g_vh;

    const int ar = tid >> 1, aseg = (tid & 1) * 4;   // row 0..127, 4 lines of 16B

    const int wm = wid & 3, wn = wid >> 2;
    const int lrow = lane & 15, lkhi = (lane >> 4) * 16;
    const int b_n  = (lane >> 4) * 8 + (lane & 7);
    const int b_k16 = ((lane >> 3) & 1) * 16;

    float acc[2][8][4];
#pragma unroll
    for (int i = 0; i < 2; i++)
#pragma unroll
        for (int j = 0; j < 8; j++)
#pragma unroll
            for (int c = 0; c < 4; c++) acc[i][j][c] = 0.0f;

    const __half* asrc_base = g_xh + (size_t)(m0 + ar) * D_ + aseg * 8;
    const __half* bsrc_base = Wth + (size_t)(n0 + ar) * D_ + aseg * 8;

    // prologue: stages 0,1
#pragma unroll
    for (int p = 0; p < 2; p++) {
        const int k0 = p * 64;
        const uint32_t so = p * 16384;
#pragma unroll
        for (int q = 0; q < 4; q++) {
            uint32_t byte = SWZ((uint32_t)ar * 128u + (aseg + q) * 16u);
            cpasync16(sA + so + byte, asrc_base + k0 + q * 8);
            cpasync16(sB + so + byte, bsrc_base + k0 + q * 8);
        }
        CP_COMMIT();
    }

    for (int kt = 0; kt < 12; kt++) {
        if (kt < 11) CP_WAIT1(); else CP_WAIT0();
        __syncthreads();
        if (kt + 2 < 12) {
            const int k0 = (kt + 2) * 64;
            const uint32_t so = ((kt + 2) % 3) * 16384;
#pragma unroll
            for (int q = 0; q < 4; q++) {
                uint32_t byte = SWZ((uint32_t)ar * 128u + (aseg + q) * 16u);
                cpasync16(sA + so + byte, asrc_base + k0 + q * 8);
                cpasync16(sB + so + byte, bsrc_base + k0 + q * 8);
            }
            CP_COMMIT();
        }

        const uint32_t a_base = sA + (kt % 3) * 16384;
        const uint32_t b_base = sB + (kt % 3) * 16384;
#pragma unroll
        for (int ks = 0; ks < 4; ks++) {
            uint32_t a0[4], a1[4];
            ldsm4(a0, a_base + SWZ((uint32_t)(wm*32 + lrow) * 128u + ks*32 + lkhi));
            ldsm4(a1, a_base + SWZ((uint32_t)(wm*32 + 16 + lrow) * 128u + ks*32 + lkhi));
#pragma unroll
            for (int jp = 0; jp < 4; jp++) {
                uint32_t bb[4];
                ldsm4(bb, b_base + SWZ((uint32_t)(wn*64 + jp*16 + b_n) * 128u + ks*32 + b_k16));
                mma16816(acc[0][jp*2+0], a0, bb+0);
                mma16816(acc[0][jp*2+1], a0, bb+2);
                mma16816(acc[1][jp*2+0], a1, bb+0);
                mma16816(acc[1][jp*2+1], a1, bb+2);
            }
        }
    }

    // epilogue: bias add, write head-major fp16
    const int g = lane >> 2, c2 = (lane & 3) * 2;
    const int h = (n0 >> 6) + wn;                    // warp's 64-col span = one head
#pragma unroll
    for (int i = 0; i < 2; i++) {
#pragma unroll
        for (int j = 0; j < 8; j++) {
            int col = j * 8 + c2;                    // dh within head
            float bz0 = bias[h * 64 + col], bz1 = bias[h * 64 + col + 1];
            int row = m0 + wm * 32 + i * 16 + g;
            int bb = row >> 11, ss = row & 2047;
            *(__half2*)&dst[(((size_t)bb * H_ + h) * S_ + ss) * HD_ + col] =
                __floats2half2_rn(acc[i][j][0] + bz0, acc[i][j][1] + bz1);
            row += 8; bb = row >> 11; ss = row & 2047;
            *(__half2*)&dst[(((size_t)bb * H_ + h) * S_ + ss) * HD_ + col] =
                __floats2half2_rn(acc[i][j][2] + bz0, acc[i][j][3] + bz1);
        }
    }
}

// ============================ attention (fp16 mma.sync, 32q warp tiles, key-split) ============================
// block: one (b,h), 128 queries, 256 threads = 8 warps = 4 m-warps (32 q) x 2 key-groups (64 keys).
// Each K/V fragment load feeds TWO m16 accumulators -> ldmatrix traffic halved vs r10.
// 2-stage cp.async ring. End: cross-group O / lsum reduction via smem.
// smem: Q@0 16KB, K0@16384, K1@32768, V0@49152, V1@65536, mask0@81920, mask1@82432
#define ATT_SMEM 82944

__global__ __launch_bounds__(256, 1) void attn_h(
    const float* __restrict__ mask, float* __restrict__ out)
{
    extern __shared__ char sm[];
    const uint32_t sQ = smem_u32(sm);
    const uint32_t sK = sQ + 16384;
    const uint32_t sV = sQ + 49152;
    const uint32_t sM = sQ + 81920;

    const int tid = threadIdx.x, wid = tid >> 5, lane = tid & 31;
    const int wq = wid & 3;          // m-warp: rows wq*32..+31
    const int kg = wid >> 2;         // key group: keys kg*64..+63 of each tile
    const int bh = blockIdx.y;
    const int b  = bh / H_;
    const int h  = bh % H_;
    const int q0 = blockIdx.x * 128;

    const __half* Qg = g_qh + (size_t)bh * S_ * HD_;
    const __half* Kg = g_kh + (size_t)bh * S_ * HD_;
    const __half* Vg = g_vh + (size_t)bh * S_ * HD_;
    const float* mrow = mask + (size_t)b * S_;

    const int lr = tid >> 1, lseg = (tid & 1) * 4;

    // load Q tile [128][64] swizzled (plain stores)
    {
        const uint4* src = (const uint4*)(Qg + (size_t)(q0 + lr) * HD_);
#pragma unroll
        for (int q = 0; q < 4; q++) {
            uint4 v = src[lseg + q];
            *(uint4*)(sm + SWZ((uint32_t)lr * 128u + (lseg + q) * 16u)) = v;
        }
    }

    // prologue: stage 0 of K/V/mask
    {
        const __half* ksrc = Kg + (size_t)lr * HD_ + lseg * 8;
        const __half* vsrc = Vg + (size_t)lr * HD_ + lseg * 8;
#pragma unroll
        for (int q = 0; q < 4; q++) {
            uint32_t byte = SWZ((uint32_t)lr * 128u + (lseg + q) * 16u);
            cpasync16(sK + byte, ksrc + q * 8);
            cpasync16(sV + byte, vsrc + q * 8);
        }
        if (tid < 32) cpasync16(sM + tid * 16, mrow + tid * 4);
        CP_COMMIT();
    }
    __syncthreads();   // Q visible for ldmatrix

    const int lrow = lane & 15, lkhi = (lane >> 4) * 16;
    const int b_n  = (lane >> 4) * 8 + (lane & 7);
    const int b_k16 = ((lane >> 3) & 1) * 16;

    // Q fragments register-resident: two m16 tiles (rows wq*32 and wq*32+16)
    uint32_t qf[2][4][4];
#pragma unroll
    for (int mt = 0; mt < 2; mt++)
#pragma unroll
        for (int ks = 0; ks < 4; ks++)
            ldsm4(qf[mt][ks], sQ + SWZ((uint32_t)(wq*32 + mt*16 + lrow) * 128u + ks*32 + lkhi));

    float o[2][8][4];
#pragma unroll
    for (int mt = 0; mt < 2; mt++)
#pragma unroll
        for (int j = 0; j < 8; j++)
#pragma unroll
            for (int c = 0; c < 4; c++) o[mt][j][c] = 0.0f;
    float lsA[2] = {0.0f, 0.0f}, lsB[2] = {0.0f, 0.0f};

    const int g = lane >> 2, c2 = (lane & 3) * 2;

    for (int kt = 0; kt < 16; kt++) {
        const int s = kt & 1;
        if (kt < 15) {
            const uint32_t so = (s ^ 1) * 16384;
            const __half* ksrc = Kg + (size_t)((kt+1)*128 + lr) * HD_ + lseg * 8;
            const __half* vsrc = Vg + (size_t)((kt+1)*128 + lr) * HD_ + lseg * 8;
#pragma unroll
            for (int q = 0; q < 4; q++) {
                uint32_t byte = SWZ((uint32_t)lr * 128u + (lseg + q) * 16u);
                cpasync16(sK + so + byte, ksrc + q * 8);
                cpasync16(sV + so + byte, vsrc + q * 8);
            }
            if (tid < 32) cpasync16(sM + (s ^ 1) * 512 + tid * 16, mrow + (kt+1)*128 + tid * 4);
            CP_COMMIT();
            CP_WAIT1();
        } else {
            CP_WAIT0();
        }
        __syncthreads();

        const uint32_t kb = sK + s * 16384;
        const uint32_t vb = sV + s * 16384;
        const float* maskS = (const float*)(sm + 81920 + s * 512);

        // two 32-key half-passes over this warp's 64 keys
#pragma unroll
        for (int hf = 0; hf < 2; hf++) {
            const int kbase = kg * 64 + hf * 32;

            // scores for 32 keys x 32 q rows: 2 m-tiles x 4 n8-tiles
            float sc[2][4][4];
#pragma unroll
            for (int mt = 0; mt < 2; mt++)
#pragma unroll
                for (int t = 0; t < 4; t++)
#pragma unroll
                    for (int c = 0; c < 4; c++) sc[mt][t][c] = 0.0f;

#pragma unroll
            for (int ks = 0; ks < 4; ks++) {
#pragma unroll
                for (int jp = 0; jp < 2; jp++) {
                    uint32_t bb[4];
                    ldsm4(bb, kb + SWZ((uint32_t)(kbase + jp*16 + b_n) * 128u + ks*32 + b_k16));
                    mma16816(sc[0][jp*2+0], qf[0][ks], bb+0);
                    mma16816(sc[0][jp*2+1], qf[0][ks], bb+2);
                    mma16816(sc[1][jp*2+0], qf[1][ks], bb+0);
                    mma16816(sc[1][jp*2+1], qf[1][ks], bb+2);
                }
            }

            // softmax (no max subtraction): p = exp2(s*0.125*log2e + m*log2e)
            uint32_t pf[2][2][4];
#pragma unroll
            for (int mt = 0; mt < 2; mt++) {
#pragma unroll
                for (int jp = 0; jp < 2; jp++) {
                    float pe[4], po[4];
                    {
                        int tt = jp * 2;
                        float m0v = maskS[kbase + tt*8 + c2] * LOG2E;
                        float m1v = maskS[kbase + tt*8 + c2 + 1] * LOG2E;
                        pe[0] = ex2(fmaf(sc[mt][tt][0], SCL2E, m0v));
                        pe[1] = ex2(fmaf(sc[mt][tt][1], SCL2E, m1v));
                        pe[2] = ex2(fmaf(sc[mt][tt][2], SCL2E, m0v));
                        pe[3] = ex2(fmaf(sc[mt][tt][3], SCL2E, m1v));
                    }
                    {
                        int tt = jp * 2 + 1;
                        float m0v = maskS[kbase + tt*8 + c2] * LOG2E;
                        float m1v = maskS[kbase + tt*8 + c2 + 1] * LOG2E;
                        po[0] = ex2(fmaf(sc[mt][tt][0], SCL2E, m0v));
                        po[1] = ex2(fmaf(sc[mt][tt][1], SCL2E, m1v));
                        po[2] = ex2(fmaf(sc[mt][tt][2], SCL2E, m0v));
                        po[3] = ex2(fmaf(sc[mt][tt][3], SCL2E, m1v));
                    }
                    lsA[mt] += pe[0] + pe[1] + po[0] + po[1];
                    lsB[mt] += pe[2] + pe[3] + po[2] + po[3];
                    pf[mt][jp][0] = packh2(pe[0], pe[1]);
                    pf[mt][jp][1] = packh2(pe[2], pe[3]);
                    pf[mt][jp][2] = packh2(po[0], po[1]);
                    pf[mt][jp][3] = packh2(po[2], po[3]);
                }
            }

            // O += P_half @ V_half : 2 k16 steps over these 32 keys, 8 d-tiles
#pragma unroll
            for (int ks2 = 0; ks2 < 2; ks2++) {
#pragma unroll
                for (int pp = 0; pp < 4; pp++) {
                    uint32_t bb[4];
                    uint32_t key = (uint32_t)(kbase + ks2*16 + ((lane>>3)&1)*8 + (lane&7));
                    uint32_t byte = (uint32_t)(2*pp + (lane>>4)) * 16u;
                    ldsm4t(bb, vb + SWZ(key * 128u + byte));
                    mma16816(o[0][pp*2+0], pf[0][ks2], bb+0);
                    mma16816(o[0][pp*2+1], pf[0][ks2], bb+2);
                    mma16816(o[1][pp*2+0], pf[1][ks2], bb+0);
                    mma16816(o[1][pp*2+1], pf[1][ks2], bb+2);
                }
            }
        }
        __syncthreads();   // everyone done with stage s before it is refilled
    }

    // reduce row sums across the 4-thread quad (within this warp's 64 keys)
#pragma unroll
    for (int mt = 0; mt < 2; mt++) {
        lsA[mt] += __shfl_xor_sync(0xffffffffu, lsA[mt], 1);
        lsA[mt] += __shfl_xor_sync(0xffffffffu, lsA[mt], 2);
        lsB[mt] += __shfl_xor_sync(0xffffffffu, lsB[mt], 1);
        lsB[mt] += __shfl_xor_sync(0xffffffffu, lsB[mt], 2);
    }

    // cross-group reduction via smem (reuse dead K/V stage region)
    float* stageO = (float*)(sm + 16384);          // [128][66] f32
    float* lred   = (float*)(sm + 16384 + 33792);  // [128] f32

    __syncthreads();   // all reads of K/V stages complete before overwrite
    if (kg == 1) {
#pragma unroll
        for (int mt = 0; mt < 2; mt++) {
            const int r = wq * 32 + mt * 16 + g;
#pragma unroll
            for (int j = 0; j < 8; j++) {
                int col = j * 8 + c2;
                stageO[r * 66 + col]         = o[mt][j][0];
                stageO[r * 66 + col + 1]     = o[mt][j][1];
                stageO[(r+8) * 66 + col]     = o[mt][j][2];
                stageO[(r+8) * 66 + col + 1] = o[mt][j][3];
            }
            if ((lane & 3) == 0) { lred[r] = lsA[mt]; lred[r + 8] = lsB[mt]; }
        }
    }
    __syncthreads();

    if (kg == 0) {
#pragma unroll
        for (int mt = 0; mt < 2; mt++) {
            const int r = wq * 32 + mt * 16 + g;
            const float inv0 = 1.0f / (lsA[mt] + lred[r]);
            const float inv1 = 1.0f / (lsB[mt] + lred[r + 8]);
            float* out0 = out + ((size_t)b * S_ + q0 + r) * D_ + h * HD_;
            float* out1 = out + ((size_t)b * S_ + q0 + r + 8) * D_ + h * HD_;
#pragma unroll
            for (int j = 0; j < 8; j++) {
                int d = j * 8 + c2;
                float2 v0 = make_float2((o[mt][j][0] + stageO[r*66 + d]) * inv0,
                                        (o[mt][j][1] + stageO[r*66 + d + 1]) * inv0);
                float2 v1 = make_float2((o[mt][j][2] + stageO[(r+8)*66 + d]) * inv1,
                                        (o[mt][j][3] + stageO[(r+8)*66 + d + 1]) * inv1);
                *(float2*)&out0[d] = v0;
                *(float2*)&out1[d] = v1;
            }
        }
    }
}

// ============================ launch ============================
extern "C" void kernel_launch(void* const* d_in, const int* in_sizes, int n_in,
                              void* d_out, int out_size)
{
    const float* v1   = (const float*)d_in[0];
    const float* mask = (const float*)d_in[1];
    const float* Wq   = (const float*)d_in[2];
    const float* bq   = (const float*)d_in[3];
    const float* Wk   = (const float*)d_in[4];
    const float* bk   = (const float*)d_in[5];
    const float* Wv   = (const float*)d_in[6];
    const float* bv   = (const float*)d_in[7];
    float* out = (float*)d_out;

    convert_x<<<NTOK * D_ / 1024, 256>>>(v1);
    convert_w<<<dim3(D_/32, D_/32, 3), dim3(32, 8)>>>(Wq, Wk, Wv);

    cudaFuncSetAttribute(qkv_gemm_h, cudaFuncAttributeMaxDynamicSharedMemorySize, GEMM_SMEM);
    qkv_gemm_h<<<dim3(NTOK/128, D_/128, 3), 256, GEMM_SMEM>>>(bq, bk, bv);

    cudaFuncSetAttribute(attn_h, cudaFuncAttributeMaxDynamicSharedMemorySize, ATT_SMEM);
    attn_h<<<dim3(S_/128, B_*H_), 256, ATT_SMEM>>>(mask, out);
}

// round 13
// speedup vs baseline: 1.0156x; 1.0156x over previous
#include <cuda_runtime.h>
#include <cuda_fp16.h>
#include <cstdint>

#define B_   2
#define S_   2048
#define D_   768
#define H_   12
#define HD_  64
#define NTOK (B_*S_)

// fp16 staging buffers
__device__ __half g_xh[NTOK*D_];     // X fp16 [m][k]
__device__ __half g_wt[3*D_*D_];     // W^T fp16 [z][n][k]
__device__ __half g_qh[NTOK*D_];     // [bh][s][64]
__device__ __half g_kh[NTOK*D_];
__device__ __half g_vh[NTOK*D_];
__device__ float  g_mf[B_*S_];       // mask * log2(e), f32

#define SWZ(b) ((b) ^ (((b)>>3)&0x70))

__device__ __forceinline__ uint32_t smem_u32(const void* p){
    uint32_t a;
    asm("{ .reg .u64 t; cvta.to.shared.u64 t, %1; cvt.u32.u64 %0, t; }" : "=r"(a) : "l"(p));
    return a;
}
__device__ __forceinline__ void ldsm4(uint32_t* r, uint32_t a){
    asm volatile("ldmatrix.sync.aligned.m8n8.x4.shared.b16 {%0,%1,%2,%3}, [%4];"
        : "=r"(r[0]),"=r"(r[1]),"=r"(r[2]),"=r"(r[3]) : "r"(a));
}
__device__ __forceinline__ void ldsm4t(uint32_t* r, uint32_t a){
    asm volatile("ldmatrix.sync.aligned.m8n8.x4.trans.shared.b16 {%0,%1,%2,%3}, [%4];"
        : "=r"(r[0]),"=r"(r[1]),"=r"(r[2]),"=r"(r[3]) : "r"(a));
}
__device__ __forceinline__ void mma16816(float* d, const uint32_t* a, const uint32_t* b){
    asm volatile(
        "mma.sync.aligned.m16n8k16.row.col.f32.f16.f16.f32 "
        "{%0,%1,%2,%3}, {%4,%5,%6,%7}, {%8,%9}, {%0,%1,%2,%3};"
        : "+f"(d[0]),"+f"(d[1]),"+f"(d[2]),"+f"(d[3])
        : "r"(a[0]),"r"(a[1]),"r"(a[2]),"r"(a[3]), "r"(b[0]),"r"(b[1]));
}
__device__ __forceinline__ uint32_t packh2(float x, float y){
    __half2 h = __floats2half2_rn(x, y);
    return *(uint32_t*)&h;
}
__device__ __forceinline__ uint32_t ex2h2(uint32_t x){
    uint32_t y; asm("ex2.approx.f16x2 %0, %1;" : "=r"(y) : "r"(x)); return y;
}
__device__ __forceinline__ uint32_t hadd2u(uint32_t a, uint32_t b){
    __half2 r = __hadd2(*(__half2*)&a, *(__half2*)&b);
    return *(uint32_t*)&r;
}
__device__ __forceinline__ void cpasync16(uint32_t dst, const void* src){
    asm volatile("cp.async.cg.shared.global [%0], [%1], 16;" :: "r"(dst), "l"(src));
}
#define CP_COMMIT() asm volatile("cp.async.commit_group;" ::: "memory")
#define CP_WAIT1()  asm volatile("cp.async.wait_group 1;" ::: "memory")
#define CP_WAIT0()  asm volatile("cp.async.wait_group 0;" ::: "memory")

#define LOG2E 1.4426950408889634f
#define SCL2E 0.1803368801111437f   /* 0.125 * log2(e) */

// ============================ convert X -> fp16 ============================
__global__ __launch_bounds__(256) void convert_x(const float* __restrict__ X){
    int i = (blockIdx.x * 256 + threadIdx.x) * 4;
    float4 v = *(const float4*)(X + i);
    uint2 u;
    u.x = packh2(v.x, v.y);
    u.y = packh2(v.z, v.w);
    *(uint2*)&g_xh[i] = u;
}

// ============================ convert mask -> mask*log2e (f32) ============================
__global__ __launch_bounds__(256) void convert_mask(const float* __restrict__ M){
    int i = (blockIdx.x * 256 + threadIdx.x) * 4;
    float4 v = *(const float4*)(M + i);
    v.x *= LOG2E; v.y *= LOG2E; v.z *= LOG2E; v.w *= LOG2E;
    *(float4*)&g_mf[i] = v;
}

// ============================ convert W -> W^T fp16 ============================
__global__ __launch_bounds__(256) void convert_w(
    const float* __restrict__ Wq, const float* __restrict__ Wk, const float* __restrict__ Wv)
{
    __shared__ float t[32][33];
    const int z = blockIdx.z;
    const float* W = (z==0) ? Wq : (z==1) ? Wk : Wv;
    __half* out = g_wt + (size_t)z * D_ * D_;
    const int n0 = blockIdx.x * 32, k0 = blockIdx.y * 32;
    const int tx = threadIdx.x, ty = threadIdx.y;   // 32 x 8
#pragma unroll
    for (int i = 0; i < 32; i += 8)
        t[ty + i][tx] = W[(size_t)(k0 + ty + i) * D_ + n0 + tx];
    __syncthreads();
#pragma unroll
    for (int i = 0; i < 32; i += 8)
        out[(size_t)(n0 + ty + i) * D_ + k0 + tx] = __float2half_rn(t[tx][ty + i]);
}

// ============================ QKV GEMM (fp16 mma.sync, 3-stage cp.async) ============================
#define GEMM_SMEM 98304

__global__ __launch_bounds__(256, 2) void qkv_gemm_h(
    const float* __restrict__ bq, const float* __restrict__ bk, const float* __restrict__ bv)
{
    extern __shared__ char sm[];
    const uint32_t sA = smem_u32(sm);            // 3 x 16KB
    const uint32_t sB = sA + 49152;              // 3 x 16KB

    const int tid = threadIdx.x, wid = tid >> 5, lane = tid & 31;
    const int z  = blockIdx.z;
    const int m0 = blockIdx.x * 128;
    const int n0 = blockIdx.y * 128;

    const __half* Wth = g_wt + (size_t)z * D_ * D_;
    const float* bias = (z==0) ? bq : (z==1) ? bk : bv;
    __half* dst = (z==0) ? g_qh : (z==1) ? g_kh : g_vh;

    const int ar = tid >> 1, aseg = (tid & 1) * 4;

    const int wm = wid & 3, wn = wid >> 2;
    const int lrow = lane & 15, lkhi = (lane >> 4) * 16;
    const int b_n  = (lane >> 4) * 8 + (lane & 7);
    const int b_k16 = ((lane >> 3) & 1) * 16;

    float acc[2][8][4];
#pragma unroll
    for (int i = 0; i < 2; i++)
#pragma unroll
        for (int j = 0; j < 8; j++)
#pragma unroll
            for (int c = 0; c < 4; c++) acc[i][j][c] = 0.0f;

    const __half* asrc_base = g_xh + (size_t)(m0 + ar) * D_ + aseg * 8;
    const __half* bsrc_base = Wth + (size_t)(n0 + ar) * D_ + aseg * 8;

#pragma unroll
    for (int p = 0; p < 2; p++) {
        const int k0 = p * 64;
        const uint32_t so = p * 16384;
#pragma unroll
        for (int q = 0; q < 4; q++) {
            uint32_t byte = SWZ((uint32_t)ar * 128u + (aseg + q) * 16u);
            cpasync16(sA + so + byte, asrc_base + k0 + q * 8);
            cpasync16(sB + so + byte, bsrc_base + k0 + q * 8);
        }
        CP_COMMIT();
    }

    for (int kt = 0; kt < 12; kt++) {
        if (kt < 11) CP_WAIT1(); else CP_WAIT0();
        __syncthreads();
        if (kt + 2 < 12) {
            const int k0 = (kt + 2) * 64;
            const uint32_t so = ((kt + 2) % 3) * 16384;
#pragma unroll
            for (int q = 0; q < 4; q++) {
                uint32_t byte = SWZ((uint32_t)ar * 128u + (aseg + q) * 16u);
                cpasync16(sA + so + byte, asrc_base + k0 + q * 8);
                cpasync16(sB + so + byte, bsrc_base + k0 + q * 8);
            }
            CP_COMMIT();
        }

        const uint32_t a_base = sA + (kt % 3) * 16384;
        const uint32_t b_base = sB + (kt % 3) * 16384;
#pragma unroll
        for (int ks = 0; ks < 4; ks++) {
            uint32_t a0[4], a1[4];
            ldsm4(a0, a_base + SWZ((uint32_t)(wm*32 + lrow) * 128u + ks*32 + lkhi));
            ldsm4(a1, a_base + SWZ((uint32_t)(wm*32 + 16 + lrow) * 128u + ks*32 + lkhi));
#pragma unroll
            for (int jp = 0; jp < 4; jp++) {
                uint32_t bb[4];
                ldsm4(bb, b_base + SWZ((uint32_t)(wn*64 + jp*16 + b_n) * 128u + ks*32 + b_k16));
                mma16816(acc[0][jp*2+0], a0, bb+0);
                mma16816(acc[0][jp*2+1], a0, bb+2);
                mma16816(acc[1][jp*2+0], a1, bb+0);
                mma16816(acc[1][jp*2+1], a1, bb+2);
            }
        }
    }

    const int g = lane >> 2, c2 = (lane & 3) * 2;
    const int h = (n0 >> 6) + wn;
#pragma unroll
    for (int i = 0; i < 2; i++) {
#pragma unroll
        for (int j = 0; j < 8; j++) {
            int col = j * 8 + c2;
            float bz0 = bias[h * 64 + col], bz1 = bias[h * 64 + col + 1];
            int row = m0 + wm * 32 + i * 16 + g;
            int bb = row >> 11, ss = row & 2047;
            *(__half2*)&dst[(((size_t)bb * H_ + h) * S_ + ss) * HD_ + col] =
                __floats2half2_rn(acc[i][j][0] + bz0, acc[i][j][1] + bz1);
            row += 8; bb = row >> 11; ss = row & 2047;
            *(__half2*)&dst[(((size_t)bb * H_ + h) * S_ + ss) * HD_ + col] =
                __floats2half2_rn(acc[i][j][2] + bz0, acc[i][j][3] + bz1);
        }
    }
}

// ============================ attention (fp16 mma.sync, 2-stage, h2 exp) ============================
// r9 shape: 256 threads, 128-q tile, two 64-key half-passes, 2 CTAs/SM.
// exp via ex2.approx.f16x2 (half the MUFU ops), lsum via HADD2.
// smem: Q@0 16KB, K0@16384, K1@32768, V0@49152, V1@65536, mask0@81920, mask1@82432
#define ATT_SMEM 82944

__global__ __launch_bounds__(256, 2) void attn_h(float* __restrict__ out)
{
    extern __shared__ char sm[];
    const uint32_t sQ = smem_u32(sm);
    const uint32_t sK = sQ + 16384;
    const uint32_t sV = sQ + 49152;
    const uint32_t sM = sQ + 81920;

    const int tid = threadIdx.x, wid = tid >> 5, lane = tid & 31;
    const int bh = blockIdx.y;
    const int b  = bh / H_;
    const int h  = bh % H_;
    const int q0 = blockIdx.x * 128;

    const __half* Qg = g_qh + (size_t)bh * S_ * HD_;
    const __half* Kg = g_kh + (size_t)bh * S_ * HD_;
    const __half* Vg = g_vh + (size_t)bh * S_ * HD_;
    const float* mrow = g_mf + (size_t)b * S_;

    const int lr = tid >> 1, lseg = (tid & 1) * 4;

    // load Q tile [128][64] swizzled
    {
        const uint4* src = (const uint4*)(Qg + (size_t)(q0 + lr) * HD_);
#pragma unroll
        for (int q = 0; q < 4; q++) {
            uint4 v = src[lseg + q];
            *(uint4*)(sm + SWZ((uint32_t)lr * 128u + (lseg + q) * 16u)) = v;
        }
    }

    // prologue: stage 0 of K/V/mask
    {
        const __half* ksrc = Kg + (size_t)lr * HD_ + lseg * 8;
        const __half* vsrc = Vg + (size_t)lr * HD_ + lseg * 8;
#pragma unroll
        for (int q = 0; q < 4; q++) {
            uint32_t byte = SWZ((uint32_t)lr * 128u + (lseg + q) * 16u);
            cpasync16(sK + byte, ksrc + q * 8);
            cpasync16(sV + byte, vsrc + q * 8);
        }
        if (tid < 32) cpasync16(sM + tid * 16, mrow + tid * 4);
        CP_COMMIT();
    }
    __syncthreads();   // Q visible for ldmatrix

    const int lrow = lane & 15, lkhi = (lane >> 4) * 16;
    const int b_n  = (lane >> 4) * 8 + (lane & 7);
    const int b_k16 = ((lane >> 3) & 1) * 16;

    uint32_t qf[4][4];
#pragma unroll
    for (int ks = 0; ks < 4; ks++)
        ldsm4(qf[ks], sQ + SWZ((uint32_t)(wid*16 + lrow) * 128u + ks*32 + lkhi));

    float o[8][4];
#pragma unroll
    for (int j = 0; j < 8; j++)
#pragma unroll
        for (int c = 0; c < 4; c++) o[j][c] = 0.0f;
    float lsum0 = 0.0f, lsum1 = 0.0f;

    const int g = lane >> 2, c2 = (lane & 3) * 2;

    for (int kt = 0; kt < 16; kt++) {
        const int s = kt & 1;
        if (kt < 15) {
            const uint32_t so = (s ^ 1) * 16384;
            const __half* ksrc = Kg + (size_t)((kt+1)*128 + lr) * HD_ + lseg * 8;
            const __half* vsrc = Vg + (size_t)((kt+1)*128 + lr) * HD_ + lseg * 8;
#pragma unroll
            for (int q = 0; q < 4; q++) {
                uint32_t byte = SWZ((uint32_t)lr * 128u + (lseg + q) * 16u);
                cpasync16(sK + so + byte, ksrc + q * 8);
                cpasync16(sV + so + byte, vsrc + q * 8);
            }
            if (tid < 32) cpasync16(sM + (s ^ 1) * 512 + tid * 16, mrow + (kt+1)*128 + tid * 4);
            CP_COMMIT();
            CP_WAIT1();
        } else {
            CP_WAIT0();
        }
        __syncthreads();

        const uint32_t kb = sK + s * 16384;
        const uint32_t vb = sV + s * 16384;
        const float* maskS = (const float*)(sm + 81920 + s * 512);

        // two half-passes over the 128 keys: scores -> exp (f16x2) -> PV
#pragma unroll
        for (int hf = 0; hf < 2; hf++) {
            float sc[8][4];
#pragma unroll
            for (int t = 0; t < 8; t++)
#pragma unroll
                for (int c = 0; c < 4; c++) sc[t][c] = 0.0f;

#pragma unroll
            for (int ks = 0; ks < 4; ks++) {
#pragma unroll
                for (int jp = 0; jp < 4; jp++) {
                    uint32_t bb[4];
                    ldsm4(bb, kb + SWZ((uint32_t)(hf*64 + jp*16 + b_n) * 128u + ks*32 + b_k16));
                    mma16816(sc[jp*2+0], qf[ks], bb+0);
                    mma16816(sc[jp*2+1], qf[ks], bb+2);
                }
            }

            // softmax (no max subtraction), exp in f16x2: p = exp2(s*SCL2E + m*log2e)
            uint32_t pf[4][4];
            uint32_t hacc0 = 0u, hacc1 = 0u;   // half2 zero
#pragma unroll
            for (int jp = 0; jp < 4; jp++) {
                {
                    int tt = jp * 2;
                    float m0v = maskS[hf*64 + tt*8 + c2];
                    float m1v = maskS[hf*64 + tt*8 + c2 + 1];
                    pf[jp][0] = ex2h2(packh2(fmaf(sc[tt][0], SCL2E, m0v),
                                             fmaf(sc[tt][1], SCL2E, m1v)));
                    pf[jp][1] = ex2h2(packh2(fmaf(sc[tt][2], SCL2E, m0v),
                                             fmaf(sc[tt][3], SCL2E, m1v)));
                }
                {
                    int tt = jp * 2 + 1;
                    float m0v = maskS[hf*64 + tt*8 + c2];
                    float m1v = maskS[hf*64 + tt*8 + c2 + 1];
                    pf[jp][2] = ex2h2(packh2(fmaf(sc[tt][0], SCL2E, m0v),
                                             fmaf(sc[tt][1], SCL2E, m1v)));
                    pf[jp][3] = ex2h2(packh2(fmaf(sc[tt][2], SCL2E, m0v),
                                             fmaf(sc[tt][3], SCL2E, m1v)));
                }
                hacc0 = hadd2u(hacc0, hadd2u(pf[jp][0], pf[jp][2]));
                hacc1 = hadd2u(hacc1, hadd2u(pf[jp][1], pf[jp][3]));
            }
            {
                __half2 h0 = *(__half2*)&hacc0, h1 = *(__half2*)&hacc1;
                lsum0 += __low2float(h0) + __high2float(h0);
                lsum1 += __low2float(h1) + __high2float(h1);
            }

            // O += P_half @ V_half
#pragma unroll
            for (int ks2 = 0; ks2 < 4; ks2++) {
#pragma unroll
                for (int pp = 0; pp < 4; pp++) {
                    uint32_t bb[4];
                    uint32_t key = (uint32_t)(hf*64 + ks2*16 + ((lane>>3)&1)*8 + (lane&7));
                    uint32_t byte = (uint32_t)(2*pp + (lane>>4)) * 16u;
                    ldsm4t(bb, vb + SWZ(key * 128u + byte));
                    mma16816(o[pp*2+0], pf[ks2], bb+0);
                    mma16816(o[pp*2+1], pf[ks2], bb+2);
                }
            }
        }
        __syncthreads();
    }

    lsum0 += __shfl_xor_sync(0xffffffffu, lsum0, 1);
    lsum0 += __shfl_xor_sync(0xffffffffu, lsum0, 2);
    lsum1 += __shfl_xor_sync(0xffffffffu, lsum1, 1);
    lsum1 += __shfl_xor_sync(0xffffffffu, lsum1, 2);
    const float inv0 = 1.0f / lsum0, inv1 = 1.0f / lsum1;

    const int row0 = q0 + wid * 16 + g;
    float* out0 = out + ((size_t)b * S_ + row0) * D_ + h * HD_;
    float* out1 = out + ((size_t)b * S_ + row0 + 8) * D_ + h * HD_;
#pragma unroll
    for (int j = 0; j < 8; j++) {
        int d = j * 8 + c2;
        float2 v0 = make_float2(o[j][0] * inv0, o[j][1] * inv0);
        float2 v1 = make_float2(o[j][2] * inv1, o[j][3] * inv1);
        *(float2*)&out0[d] = v0;
        *(float2*)&out1[d] = v1;
    }
}

// ============================ launch ============================
extern "C" void kernel_launch(void* const* d_in, const int* in_sizes, int n_in,
                              void* d_out, int out_size)
{
    const float* v1   = (const float*)d_in[0];
    const float* mask = (const float*)d_in[1];
    const float* Wq   = (const float*)d_in[2];
    const float* bq   = (const float*)d_in[3];
    const float* Wk   = (const float*)d_in[4];
    const float* bk   = (const float*)d_in[5];
    const float* Wv   = (const float*)d_in[6];
    const float* bv   = (const float*)d_in[7];
    float* out = (float*)d_out;

    convert_x<<<NTOK * D_ / 1024, 256>>>(v1);
    convert_mask<<<B_ * S_ / 1024, 256>>>(mask);
    convert_w<<<dim3(D_/32, D_/32, 3), dim3(32, 8)>>>(Wq, Wk, Wv);

    cudaFuncSetAttribute(qkv_gemm_h, cudaFuncAttributeMaxDynamicSharedMemorySize, GEMM_SMEM);
    qkv_gemm_h<<<dim3(NTOK/128, D_/128, 3), 256, GEMM_SMEM>>>(bq, bk, bv);

    cudaFuncSetAttribute(attn_h, cudaFuncAttributeMaxDynamicSharedMemorySize, ATT_SMEM);
    attn_h<<<dim3(S_/128, B_*H_), 256, ATT_SMEM>>>(out);
}